// round 7
// baseline (speedup 1.0000x reference)
#include <cuda_runtime.h>
#include <cstdint>

#define B_    32
#define C_    320
#define H_    64
#define W_    64
#define CTXD  1024
#define KIN   1026     // 1024 context channels + 2 indicator channels
#define KPAD  1056     // padded to 32-multiple for the transpose tiling
#define CHW   16
#define P_    256      // 16*16 spatial positions
#define PROWS 18       // padded rows
#define PCOLS 20       // padded cols (multiple of 4 -> aligned float4 rows)
#define PP    (PROWS * PCOLS)   // 360 floats per padded channel map
#define CICH  12       // input-channel chunk staged in SMEM

typedef unsigned long long ull;

// ---- scratch (device globals: allocation-free, zero-initialized) ----
__device__ float g_ctxT[(size_t)B_ * KPAD * P_];        // transposed ctx (B, ci, p)
__device__ float g_cx1 [((size_t)B_ * C_ + 4) * PP];    // conv1+SiLU, padded 18x20 (+4 ch pad for last-chunk overread)
__device__ float g_cx2 [(size_t)B_ * C_ * P_];          // conv2 out
__device__ int   g_bbi [B_ * 8];                        // x1,y1,x2,y2,ok,dx,dy

// ---- packed fp32x2 helpers (FFMA2: 2x fp32 FMA per issue, exact fp32) ----
__device__ __forceinline__ ull ffma2(ull a, ull b, ull c) {
    ull d;
    asm("fma.rn.f32x2 %0, %1, %2, %3;" : "=l"(d) : "l"(a), "l"(b), "l"(c));
    return d;
}
__device__ __forceinline__ ull dup2(float x) {
    ull d;
    asm("mov.b64 %0, {%1, %1};" : "=l"(d) : "f"(x), "f"(x));
    return d;
}
__device__ __forceinline__ ull pack2(float lo, float hi) {
    ull d;
    asm("mov.b64 %0, {%1, %2};" : "=l"(d) : "f"(lo), "f"(hi));
    return d;
}

// ---------------------------------------------------------------------------
// bbox -> int precompute (matches jnp: (bbox*64) truncated to int32)
// ---------------------------------------------------------------------------
__global__ void bbox_prep_kernel(const float* __restrict__ bbox) {
    int b = threadIdx.x;
    if (b >= B_) return;
    int x1 = (int)(bbox[4 * b + 0] * 64.0f);
    int y1 = (int)(bbox[4 * b + 1] * 64.0f);
    int x2 = (int)(bbox[4 * b + 2] * 64.0f);
    int y2 = (int)(bbox[4 * b + 3] * 64.0f);
    x2 = max(x2, x1 + 1);
    y2 = max(y2, y1 + 1);
    int ok = (y2 <= H_) && (x2 <= W_) && (y1 >= 0) && (x1 >= 0);
    int* o = &g_bbi[b * 8];
    o[0] = x1; o[1] = y1; o[2] = x2; o[3] = y2;
    o[4] = ok; o[5] = x2 - x1; o[6] = y2 - y1;
}

// ---------------------------------------------------------------------------
// context (B,256,1024) + indicator -> g_ctxT (B, 1056, 256)
// rows 1024/1025 = indicator, rows >=1026 = 0
// ---------------------------------------------------------------------------
__global__ void transpose_kernel(const float* __restrict__ context,
                                 const float* __restrict__ indicator) {
    __shared__ float tile[32][33];
    int b   = blockIdx.z;
    int ci0 = blockIdx.y * 32;
    int p0  = blockIdx.x * 32;
    int tx = threadIdx.x, ty = threadIdx.y;
#pragma unroll
    for (int j = 0; j < 4; ++j) {
        int p  = p0 + ty + 8 * j;
        int ci = ci0 + tx;
        float v;
        if (ci < CTXD)      v = context[((size_t)b * P_ + p) * CTXD + ci];
        else if (ci < KIN)  v = indicator[b * 2 + (ci - CTXD)];
        else                v = 0.0f;
        tile[ty + 8 * j][tx] = v;
    }
    __syncthreads();
#pragma unroll
    for (int j = 0; j < 4; ++j) {
        int ci = ci0 + ty + 8 * j;
        int p  = p0 + tx;
        g_ctxT[((size_t)b * KPAD + ci) * P_ + p] = tile[tx][ty + 8 * j];
    }
}

// ---------------------------------------------------------------------------
// Shared inner-product core: thread tile = 4 consecutive-x positions x 4 co.
// Per ci: 6 aligned LDS.128 (x rows) + 9 broadcast LDS.128 (weights)
//         feeding 72 FFMA2  -> FFMA2-pipe bound.
// ---------------------------------------------------------------------------
#define CONV_CORE(sX, sW, acc, y, x0, co_q)                                        \
    _Pragma("unroll 1")                                                            \
    for (int ci = 0; ci < CICH; ++ci) {                                            \
        _Pragma("unroll")                                                          \
        for (int r = 0; r < 3; ++r) {                                              \
            int rowbase = (y + r) * PCOLS + x0;                                    \
            float4 va = *reinterpret_cast<const float4*>(&sX[ci][rowbase]);        \
            float4 vb = *reinterpret_cast<const float4*>(&sX[ci][rowbase + 4]);    \
            ull xd[6];                                                             \
            xd[0] = dup2(va.y); xd[1] = dup2(va.z); xd[2] = dup2(va.w);            \
            xd[3] = dup2(vb.x); xd[4] = dup2(vb.y); xd[5] = dup2(vb.z);            \
            _Pragma("unroll")                                                      \
            for (int dx = 0; dx < 3; ++dx) {                                       \
                float4 wv = *reinterpret_cast<const float4*>(                      \
                    &sW[ci][r * 3 + dx][co_q * 4]);                                \
                ull w0 = pack2(wv.x, wv.y);                                        \
                ull w1 = pack2(wv.z, wv.w);                                        \
                _Pragma("unroll")                                                  \
                for (int j = 0; j < 4; ++j) {                                      \
                    acc[j][0] = ffma2(w0, xd[j + dx], acc[j][0]);                  \
                    acc[j][1] = ffma2(w1, xd[j + dx], acc[j][1]);                  \
                }                                                                  \
            }                                                                      \
        }                                                                          \
    }

// ---------------------------------------------------------------------------
// conv1 (K=1026 via 86 chunks of 12) + SiLU -> padded g_cx1 (18x20 layout)
// CTA tile: 16 out-channels x 256 positions.
// ---------------------------------------------------------------------------
__global__ __launch_bounds__(256) void conv1_kernel(const float* __restrict__ w_in,
                                                    const float* __restrict__ b_in) {
    __shared__ __align__(16) float sX[CICH][PP];
    __shared__ __align__(16) float sW[CICH][9][16];
    int t   = threadIdx.x;
    int co0 = blockIdx.x * 16;
    int b   = blockIdx.y;

    // zero the padded borders once; interior is rewritten every chunk
    for (int idx = t; idx < CICH * PP; idx += 256) {
        int q  = idx % PP;
        int qy = q / PCOLS, qx = q % PCOLS;
        if (qy == 0 || qy == 17 || qx < 2 || qx >= 18) (&sX[0][0])[idx] = 0.0f;
    }

    int co_q = t & 3;             // 4 consecutive out-channels
    int pg   = t >> 2;            // 0..63 position quad
    int y    = pg >> 2;           // 0..15
    int x0   = (pg & 3) * 4;      // 0,4,8,12

    ull acc[4][2];
#pragma unroll
    for (int i = 0; i < 4; ++i) { acc[i][0] = 0ull; acc[i][1] = 0ull; }

    const int NCH = (KIN + CICH - 1) / CICH;   // 86
    for (int ch = 0; ch < NCH; ++ch) {
        int ci0 = ch * CICH;
        __syncthreads();
        // stage X interior (coalesced from transposed layout)
        for (int idx = t; idx < CICH * P_; idx += 256) {
            int ci = idx >> 8;
            int p  = idx & 255;
            int py = p >> 4, px = p & 15;
            sX[ci][(py + 1) * PCOLS + px + 2] =
                g_ctxT[((size_t)b * KPAD + ci0 + ci) * P_ + p];
        }
        // stage W (zero past K=1026)
        for (int idx = t; idx < CICH * 9 * 16; idx += 256) {
            int co = idx & 15;
            int k  = idx >> 4;
            int ci = k / 9, tap = k - ci * 9;
            int gci = ci0 + ci;
            sW[ci][tap][co] = (gci < KIN)
                ? w_in[((size_t)(co0 + co) * KIN + gci) * 9 + tap] : 0.0f;
        }
        __syncthreads();
        CONV_CORE(sX, sW, acc, y, x0, co_q)
    }

    // epilogue: bias + SiLU, write interior of padded 18x20 map
#pragma unroll
    for (int j = 0; j < 4; ++j)
#pragma unroll
        for (int pr = 0; pr < 2; ++pr) {
            int co = co0 + co_q * 4 + pr * 2;
            ull a = acc[j][pr];
            float v0 = __uint_as_float((unsigned)(a & 0xffffffffull)) + b_in[co];
            float v1 = __uint_as_float((unsigned)(a >> 32)) + b_in[co + 1];
            float s0 = v0 / (1.0f + expf(-v0));
            float s1 = v1 / (1.0f + expf(-v1));
            size_t base = ((size_t)b * C_ + co) * PP + (y + 1) * PCOLS + x0 + j + 2;
            g_cx1[base]      = s0;
            g_cx1[base + PP] = s1;
        }
}

// ---------------------------------------------------------------------------
// conv2 (K=320 via 27 chunks of 12) -> g_cx2 (no activation)
// g_cx1 already carries the zero padding -> staging is a flat float4 copy
// ---------------------------------------------------------------------------
__global__ __launch_bounds__(256) void conv2_kernel(const float* __restrict__ w_out,
                                                    const float* __restrict__ b_out) {
    __shared__ __align__(16) float sX[CICH][PP];
    __shared__ __align__(16) float sW[CICH][9][16];
    int t   = threadIdx.x;
    int co0 = blockIdx.x * 16;
    int b   = blockIdx.y;

    int co_q = t & 3;
    int pg   = t >> 2;
    int y    = pg >> 2;
    int x0   = (pg & 3) * 4;

    ull acc[4][2];
#pragma unroll
    for (int i = 0; i < 4; ++i) { acc[i][0] = 0ull; acc[i][1] = 0ull; }

    const int NCH = (C_ + CICH - 1) / CICH;    // 27
    for (int ch = 0; ch < NCH; ++ch) {
        int ci0 = ch * CICH;
        __syncthreads();
        // flat copy incl. borders (pad channels past C_ are zero by construction)
        {
            const float4* src = reinterpret_cast<const float4*>(
                g_cx1 + ((size_t)b * C_ + ci0) * PP);
            float4* dst = reinterpret_cast<float4*>(&sX[0][0]);
            for (int idx = t; idx < CICH * PP / 4; idx += 256) dst[idx] = src[idx];
        }
        for (int idx = t; idx < CICH * 9 * 16; idx += 256) {
            int co = idx & 15;
            int k  = idx >> 4;
            int ci = k / 9, tap = k - ci * 9;
            int gci = ci0 + ci;
            sW[ci][tap][co] = (gci < C_)
                ? w_out[((size_t)(co0 + co) * C_ + gci) * 9 + tap] : 0.0f;
        }
        __syncthreads();
        CONV_CORE(sX, sW, acc, y, x0, co_q)
    }

#pragma unroll
    for (int j = 0; j < 4; ++j)
#pragma unroll
        for (int pr = 0; pr < 2; ++pr) {
            int co = co0 + co_q * 4 + pr * 2;
            ull a = acc[j][pr];
            float v0 = __uint_as_float((unsigned)(a & 0xffffffffull)) + b_out[co];
            float v1 = __uint_as_float((unsigned)(a >> 32)) + b_out[co + 1];
            size_t base = ((size_t)b * C_ + co) * P_ + y * CHW + x0 + j;
            g_cx2[base]      = v0;
            g_cx2[base + P_] = v1;
        }
}

// ---------------------------------------------------------------------------
// out = global_x + masked nearest-neighbor upsample of g_cx2 into the bbox
// ---------------------------------------------------------------------------
__global__ __launch_bounds__(256) void fuse_kernel(const float* __restrict__ gx,
                                                   float* __restrict__ out) {
    int idx = blockIdx.x * 256 + threadIdx.x;    // (bc*64 + y)*16 + xg
    int xg = idx & 15;
    int y  = (idx >> 4) & 63;
    int bc = idx >> 10;                           // b*C_ + c
    int b  = bc / C_;

    size_t gbase = (((size_t)bc * 64 + y) * 64) + xg * 4;
    float4 g = *reinterpret_cast<const float4*>(gx + gbase);

    const int* bb = &g_bbi[b * 8];
    int x1 = bb[0], y1 = bb[1], x2 = bb[2], y2 = bb[3];
    int ok = bb[4], dxs = bb[5], dys = bb[6];

    if (ok && y >= y1 && y < y2) {
        int sy = (y - y1) * CHW / dys;
        sy = min(max(sy, 0), CHW - 1);
        const float* lrow = g_cx2 + (size_t)bc * P_ + sy * CHW;
        int xb = xg * 4;
        float* gv = reinterpret_cast<float*>(&g);
#pragma unroll
        for (int k = 0; k < 4; ++k) {
            int xx = xb + k;
            if (xx >= x1 && xx < x2) {
                int sx = (xx - x1) * CHW / dxs;
                sx = min(max(sx, 0), CHW - 1);
                gv[k] += lrow[sx];
            }
        }
    }
    *reinterpret_cast<float4*>(out + gbase) = g;
}

// ---------------------------------------------------------------------------
extern "C" void kernel_launch(void* const* d_in, const int* in_sizes, int n_in,
                              void* d_out, int out_size) {
    const float* global_x  = (const float*)d_in[0];
    const float* context   = (const float*)d_in[1];
    const float* indicator = (const float*)d_in[2];
    const float* bbox      = (const float*)d_in[3];
    const float* w_in      = (const float*)d_in[4];
    const float* b_in      = (const float*)d_in[5];
    const float* w_out     = (const float*)d_in[6];
    const float* b_out     = (const float*)d_in[7];
    float* out = (float*)d_out;

    bbox_prep_kernel<<<1, 32>>>(bbox);
    transpose_kernel<<<dim3(8, 33, 32), dim3(32, 8)>>>(context, indicator);
    conv1_kernel<<<dim3(20, 32), 256>>>(w_in, b_in);
    conv2_kernel<<<dim3(20, 32), 256>>>(w_out, b_out);
    fuse_kernel<<<(B_ * C_ * H_ * (W_ / 4)) / 256, 256>>>(global_x, out);
}

// round 11
// speedup vs baseline: 1.6398x; 1.6398x over previous
#include <cuda_runtime.h>
#include <cstdint>

#define B_    32
#define C_    320
#define H_    64
#define W_    64
#define CTXD  1024
#define KIN   1026     // 1024 context channels + 2 indicator channels
#define KPAD  1056     // padded to 32-multiple for the transpose tiling
#define CHW   16
#define P_    256      // 16*16 spatial positions
#define PROWS 18       // padded rows
#define PCOLS 20       // padded cols
#define PP    (PROWS * PCOLS)   // 360 floats per padded channel map
#define CICH  12       // input-channel chunk staged in SMEM

typedef unsigned long long ull;

// ---- scratch (device globals: allocation-free, zero-initialized) ----
__device__ float g_ctxT[(size_t)B_ * KPAD * P_];        // transposed ctx (B, ci, p)
__device__ float g_cx1 [((size_t)B_ * C_ + 4) * PP];    // conv1+SiLU, padded 18x20 (+4 ch pad for overread)
__device__ float g_cx2 [(size_t)B_ * C_ * P_];          // conv2 out
__device__ int   g_bbi [B_ * 8];                        // x1,y1,x2,y2,ok,dx,dy

// ---- packed fp32x2 helpers (FFMA2: 2x fp32 FMA per issue, exact fp32) ----
__device__ __forceinline__ ull ffma2(ull a, ull b, ull c) {
    ull d;
    asm("fma.rn.f32x2 %0, %1, %2, %3;" : "=l"(d) : "l"(a), "l"(b), "l"(c));
    return d;
}
__device__ __forceinline__ ull dup2(float x) {
    ull d;
    asm("mov.b64 %0, {%1, %1};" : "=l"(d) : "f"(x), "f"(x));
    return d;
}
__device__ __forceinline__ float lo32(ull a) { return __uint_as_float((unsigned)(a & 0xffffffffull)); }
__device__ __forceinline__ float hi32(ull a) { return __uint_as_float((unsigned)(a >> 32)); }

// ---------------------------------------------------------------------------
// bbox -> int precompute (matches jnp: (bbox*64) truncated to int32)
// ---------------------------------------------------------------------------
__global__ void bbox_prep_kernel(const float* __restrict__ bbox) {
    int b = threadIdx.x;
    if (b >= B_) return;
    int x1 = (int)(bbox[4 * b + 0] * 64.0f);
    int y1 = (int)(bbox[4 * b + 1] * 64.0f);
    int x2 = (int)(bbox[4 * b + 2] * 64.0f);
    int y2 = (int)(bbox[4 * b + 3] * 64.0f);
    x2 = max(x2, x1 + 1);
    y2 = max(y2, y1 + 1);
    int ok = (y2 <= H_) && (x2 <= W_) && (y1 >= 0) && (x1 >= 0);
    int* o = &g_bbi[b * 8];
    o[0] = x1; o[1] = y1; o[2] = x2; o[3] = y2;
    o[4] = ok; o[5] = x2 - x1; o[6] = y2 - y1;
}

// ---------------------------------------------------------------------------
// context (B,256,1024) + indicator -> g_ctxT (B, 1056, 256)
// ---------------------------------------------------------------------------
__global__ void transpose_kernel(const float* __restrict__ context,
                                 const float* __restrict__ indicator) {
    __shared__ float tile[32][33];
    int b   = blockIdx.z;
    int ci0 = blockIdx.y * 32;
    int p0  = blockIdx.x * 32;
    int tx = threadIdx.x, ty = threadIdx.y;
#pragma unroll
    for (int j = 0; j < 4; ++j) {
        int p  = p0 + ty + 8 * j;
        int ci = ci0 + tx;
        float v;
        if (ci < CTXD)      v = context[((size_t)b * P_ + p) * CTXD + ci];
        else if (ci < KIN)  v = indicator[b * 2 + (ci - CTXD)];
        else                v = 0.0f;
        tile[ty + 8 * j][tx] = v;
    }
    __syncthreads();
#pragma unroll
    for (int j = 0; j < 4; ++j) {
        int ci = ci0 + ty + 8 * j;
        int p  = p0 + tx;
        g_ctxT[((size_t)b * KPAD + ci) * P_ + p] = tile[tx][ty + 8 * j];
    }
}

// ---------------------------------------------------------------------------
// Inner-product core. Thread tile = 4 consecutive-x positions x 1 y x 4 co.
// Per ci: 18 conflict-free scalar LDS (x, reused across 3 taps) +
//         18 broadcast LDS.64 (weight pairs, each reused 4x) + 72 FFMA2.
// ---------------------------------------------------------------------------
#define CONV_CORE(sX, sW, acc, y, x0, co_h)                                        \
    _Pragma("unroll 1")                                                            \
    for (int ci = 0; ci < CICH; ++ci) {                                            \
        _Pragma("unroll")                                                          \
        for (int r = 0; r < 3; ++r) {                                              \
            int rb = (y + r) * PCOLS + x0 + 1;                                     \
            ull xd[6];                                                             \
            _Pragma("unroll")                                                      \
            for (int i = 0; i < 6; ++i) xd[i] = dup2(sX[ci][rb + i]);              \
            _Pragma("unroll")                                                      \
            for (int dx = 0; dx < 3; ++dx) {                                       \
                const ull* wp = reinterpret_cast<const ull*>(                      \
                    &sW[ci][r * 3 + dx][co_h * 4]);                                \
                ull w0 = wp[0];                                                    \
                ull w1 = wp[1];                                                    \
                _Pragma("unroll")                                                  \
                for (int j = 0; j < 4; ++j) {                                      \
                    acc[j][0] = ffma2(w0, xd[dx + j], acc[j][0]);                  \
                    acc[j][1] = ffma2(w1, xd[dx + j], acc[j][1]);                  \
                }                                                                  \
            }                                                                      \
        }                                                                          \
    }

// thread mapping: co_h = t&3 (4 co each), pg = t>>2; y = pg&15, x0 = (pg>>4)*4
// -> each warp: 8 consecutive y at one x0  => x-LDS banks {20k mod 32} all distinct.

// ---------------------------------------------------------------------------
// conv1 (K=1026 via 86 chunks of 12) + SiLU -> padded g_cx1 (18x20 layout)
// CTA tile: 16 out-channels x 256 positions.
// ---------------------------------------------------------------------------
__global__ __launch_bounds__(256) void conv1_kernel(const float* __restrict__ w_in,
                                                    const float* __restrict__ b_in) {
    __shared__ float sX[CICH][PP];
    __shared__ __align__(8) float sW[CICH][9][16];
    int t   = threadIdx.x;
    int co0 = blockIdx.x * 16;
    int b   = blockIdx.y;

    // zero the padded borders once; interior is rewritten every chunk
    for (int idx = t; idx < CICH * PP; idx += 256) {
        int q  = idx % PP;
        int qy = q / PCOLS, qx = q % PCOLS;
        if (qy == 0 || qy == 17 || qx < 2 || qx >= 18) (&sX[0][0])[idx] = 0.0f;
    }

    int co_h = t & 3;
    int pg   = t >> 2;
    int y    = pg & 15;
    int x0   = (pg >> 4) * 4;

    ull acc[4][2];
#pragma unroll
    for (int i = 0; i < 4; ++i) { acc[i][0] = 0ull; acc[i][1] = 0ull; }

    const int NCH = (KIN + CICH - 1) / CICH;   // 86
    for (int ch = 0; ch < NCH; ++ch) {
        int ci0 = ch * CICH;
        __syncthreads();
        // stage X interior (coalesced from transposed layout)
        for (int idx = t; idx < CICH * P_; idx += 256) {
            int ci = idx >> 8;
            int p  = idx & 255;
            int py = p >> 4, px = p & 15;
            sX[ci][(py + 1) * PCOLS + px + 2] =
                g_ctxT[((size_t)b * KPAD + ci0 + ci) * P_ + p];
        }
        // stage W (zero past K=1026)
        for (int idx = t; idx < CICH * 9 * 16; idx += 256) {
            int co = idx & 15;
            int k  = idx >> 4;
            int ci = k / 9, tap = k - ci * 9;
            int gci = ci0 + ci;
            sW[ci][tap][co] = (gci < KIN)
                ? w_in[((size_t)(co0 + co) * KIN + gci) * 9 + tap] : 0.0f;
        }
        __syncthreads();
        CONV_CORE(sX, sW, acc, y, x0, co_h)
    }

    // epilogue: bias + SiLU; per-co float2 stores into padded interior
#pragma unroll
    for (int cp = 0; cp < 2; ++cp) {
        int co = co0 + co_h * 4 + cp * 2;
        float bl = b_in[co], bh = b_in[co + 1];
        float vl[4], vh[4];
#pragma unroll
        for (int j = 0; j < 4; ++j) {
            float a = lo32(acc[j][cp]) + bl;
            float c = hi32(acc[j][cp]) + bh;
            vl[j] = a / (1.0f + expf(-a));
            vh[j] = c / (1.0f + expf(-c));
        }
        size_t base = ((size_t)b * C_ + co) * PP + (y + 1) * PCOLS + x0 + 2;
        *reinterpret_cast<float2*>(&g_cx1[base])          = make_float2(vl[0], vl[1]);
        *reinterpret_cast<float2*>(&g_cx1[base + 2])      = make_float2(vl[2], vl[3]);
        *reinterpret_cast<float2*>(&g_cx1[base + PP])     = make_float2(vh[0], vh[1]);
        *reinterpret_cast<float2*>(&g_cx1[base + PP + 2]) = make_float2(vh[2], vh[3]);
    }
}

// ---------------------------------------------------------------------------
// conv2 (K=320 via 27 chunks of 12) -> g_cx2 (no activation)
// g_cx1 already carries zero padding -> staging is a flat float4 copy
// ---------------------------------------------------------------------------
__global__ __launch_bounds__(256) void conv2_kernel(const float* __restrict__ w_out,
                                                    const float* __restrict__ b_out) {
    __shared__ float sX[CICH][PP];
    __shared__ __align__(8) float sW[CICH][9][16];
    int t   = threadIdx.x;
    int co0 = blockIdx.x * 16;
    int b   = blockIdx.y;

    int co_h = t & 3;
    int pg   = t >> 2;
    int y    = pg & 15;
    int x0   = (pg >> 4) * 4;

    ull acc[4][2];
#pragma unroll
    for (int i = 0; i < 4; ++i) { acc[i][0] = 0ull; acc[i][1] = 0ull; }

    const int NCH = (C_ + CICH - 1) / CICH;    // 27
    for (int ch = 0; ch < NCH; ++ch) {
        int ci0 = ch * CICH;
        __syncthreads();
        {   // flat copy incl. borders (channels past C_ are zero pad)
            const float4* src = reinterpret_cast<const float4*>(
                g_cx1 + ((size_t)b * C_ + ci0) * PP);
            float4* dst = reinterpret_cast<float4*>(&sX[0][0]);
            for (int idx = t; idx < CICH * PP / 4; idx += 256) dst[idx] = src[idx];
        }
        for (int idx = t; idx < CICH * 9 * 16; idx += 256) {
            int co = idx & 15;
            int k  = idx >> 4;
            int ci = k / 9, tap = k - ci * 9;
            int gci = ci0 + ci;
            sW[ci][tap][co] = (gci < C_)
                ? w_out[((size_t)(co0 + co) * C_ + gci) * 9 + tap] : 0.0f;
        }
        __syncthreads();
        CONV_CORE(sX, sW, acc, y, x0, co_h)
    }

    // epilogue: bias; per-co float4 store (x0 is 16B-aligned in 16-wide rows)
#pragma unroll
    for (int cp = 0; cp < 2; ++cp) {
        int co = co0 + co_h * 4 + cp * 2;
        float bl = b_out[co], bh = b_out[co + 1];
        float4 vl, vh;
        vl.x = lo32(acc[0][cp]) + bl; vl.y = lo32(acc[1][cp]) + bl;
        vl.z = lo32(acc[2][cp]) + bl; vl.w = lo32(acc[3][cp]) + bl;
        vh.x = hi32(acc[0][cp]) + bh; vh.y = hi32(acc[1][cp]) + bh;
        vh.z = hi32(acc[2][cp]) + bh; vh.w = hi32(acc[3][cp]) + bh;
        size_t base = ((size_t)b * C_ + co) * P_ + y * CHW + x0;
        *reinterpret_cast<float4*>(&g_cx2[base])      = vl;
        *reinterpret_cast<float4*>(&g_cx2[base + P_]) = vh;
    }
}

// ---------------------------------------------------------------------------
// out = global_x + masked nearest-neighbor upsample of g_cx2 into the bbox
// ---------------------------------------------------------------------------
__global__ __launch_bounds__(256) void fuse_kernel(const float* __restrict__ gx,
                                                   float* __restrict__ out) {
    int idx = blockIdx.x * 256 + threadIdx.x;    // (bc*64 + y)*16 + xg
    int xg = idx & 15;
    int y  = (idx >> 4) & 63;
    int bc = idx >> 10;                           // b*C_ + c
    int b  = bc / C_;

    size_t gbase = (((size_t)bc * 64 + y) * 64) + xg * 4;
    float4 g = *reinterpret_cast<const float4*>(gx + gbase);

    const int* bb = &g_bbi[b * 8];
    int x1 = bb[0], y1 = bb[1], x2 = bb[2], y2 = bb[3];
    int ok = bb[4], dxs = bb[5], dys = bb[6];

    if (ok && y >= y1 && y < y2) {
        int sy = (y - y1) * CHW / dys;
        sy = min(max(sy, 0), CHW - 1);
        const float* lrow = g_cx2 + (size_t)bc * P_ + sy * CHW;
        int xb = xg * 4;
        float* gv = reinterpret_cast<float*>(&g);
#pragma unroll
        for (int k = 0; k < 4; ++k) {
            int xx = xb + k;
            if (xx >= x1 && xx < x2) {
                int sx = (xx - x1) * CHW / dxs;
                sx = min(max(sx, 0), CHW - 1);
                gv[k] += lrow[sx];
            }
        }
    }
    *reinterpret_cast<float4*>(out + gbase) = g;
}

// ---------------------------------------------------------------------------
extern "C" void kernel_launch(void* const* d_in, const int* in_sizes, int n_in,
                              void* d_out, int out_size) {
    const float* global_x  = (const float*)d_in[0];
    const float* context   = (const float*)d_in[1];
    const float* indicator = (const float*)d_in[2];
    const float* bbox      = (const float*)d_in[3];
    const float* w_in      = (const float*)d_in[4];
    const float* b_in      = (const float*)d_in[5];
    const float* w_out     = (const float*)d_in[6];
    const float* b_out     = (const float*)d_in[7];
    float* out = (float*)d_out;

    bbox_prep_kernel<<<1, 32>>>(bbox);
    transpose_kernel<<<dim3(8, 33, 32), dim3(32, 8)>>>(context, indicator);
    conv1_kernel<<<dim3(20, 32), 256>>>(w_in, b_in);
    conv2_kernel<<<dim3(20, 32), 256>>>(w_out, b_out);
    fuse_kernel<<<(B_ * C_ * H_ * (W_ / 4)) / 256, 256>>>(global_x, out);
}